// round 4
// baseline (speedup 1.0000x reference)
#include <cuda_runtime.h>
#include <cuda_bf16.h>

// Problem constants (fixed by the reference)
#define NN 100000      // N_NODES
#define DD 64          // D_IN == D_OUT
#define NE 1250000     // N_EDGES

// Scratch accumulator: sum of neighbor features per node (25.6 MB).
// 16B-aligned for red.global.add.v4.f32.
__device__ __align__(16) float g_aggr[NN * DD];

// ---------------------------------------------------------------------------
// Kernel 1: zero the accumulator (float4 stores)
// ---------------------------------------------------------------------------
__global__ void zero_aggr_kernel() {
    int i = blockIdx.x * blockDim.x + threadIdx.x;
    if (i < NN * (DD / 4)) {
        ((float4*)g_aggr)[i] = make_float4(0.f, 0.f, 0.f, 0.f);
    }
}

// ---------------------------------------------------------------------------
// Kernel 2: edge scatter-add.
// One thread per (edge, 16B-chunk): 16 threads cover one edge's 64 floats.
// Gather x[src] (L2-resident, 25.6MB) and red.global.add.v4.f32 into aggr[dst].
// Vector reduction (no return) keeps issue count at 20M instead of 80M.
// NOTE: edge_index is int32 on device (JAX x64 disabled downgrades int64).
// ---------------------------------------------------------------------------
__global__ void scatter_kernel(const float4* __restrict__ x4,
                               const int* __restrict__ src,
                               const int* __restrict__ dst) {
    int i = blockIdx.x * blockDim.x + threadIdx.x;
    if (i >= NE * 16) return;
    int e = i >> 4;
    int c = i & 15;
    int s = __ldg(&src[e]);   // 16 lanes share the address -> 1 request
    int d = __ldg(&dst[e]);
    float4 v = __ldg(&x4[(long)s * 16 + c]);
    float* p = g_aggr + ((long)d * DD + c * 4);
    asm volatile("red.global.add.v4.f32 [%0], {%1, %2, %3, %4};"
                 :: "l"(p), "f"(v.x), "f"(v.y), "f"(v.z), "f"(v.w)
                 : "memory");
}

// ---------------------------------------------------------------------------
// Kernel 3: fused  out = tanh(aggr @ W_l + b_l + x @ W_r)
// Tile: 64 rows x 64 cols per block, 256 threads, 4x4 register tile/thread.
// Two passes over the same shared buffers: (W_l, aggr) then (W_r, x).
// A tile stored transposed with pad-to-65 to make both load and use
// bank-conflict-free.
// ---------------------------------------------------------------------------
__global__ void fused_gemm_kernel(const float* __restrict__ x,
                                  const float* __restrict__ Wl,
                                  const float* __restrict__ bl,
                                  const float* __restrict__ Wr,
                                  float* __restrict__ out) {
    __shared__ float sW[DD * DD];        // 16 KB: current weight matrix
    __shared__ float sA[DD * 65];        // 16.25 KB: transposed A tile [k][row]

    const int tid = threadIdx.x;
    const int tx  = tid & 15;            // col group: cols tx*4 .. tx*4+3
    const int ty  = tid >> 4;            // row group: rows ty*4 .. ty*4+3
    const int row0 = blockIdx.x * 64;

    float acc[4][4];
#pragma unroll
    for (int i = 0; i < 4; ++i)
#pragma unroll
        for (int j = 0; j < 4; ++j) acc[i][j] = 0.f;

#pragma unroll
    for (int pass = 0; pass < 2; ++pass) {
        const float* W = pass ? Wr : Wl;
        const float* A = pass ? x  : g_aggr;

        // load W (64x64 f32 = 1024 float4, 4 per thread)
        {
            const float4* W4 = (const float4*)W;
            float4* sW4 = (float4*)sW;
#pragma unroll
            for (int i = 0; i < 4; ++i) sW4[tid + 256 * i] = W4[tid + 256 * i];
        }
        // load A tile, store transposed: sA[k*65 + row] = A[row0+row][k]
#pragma unroll
        for (int i = 0; i < 4; ++i) {
            int row = (tid >> 4) + i * 16;   // 0..63
            int c4  = tid & 15;              // k-chunk
            float4 v = make_float4(0.f, 0.f, 0.f, 0.f);
            if (row0 + row < NN)
                v = __ldg((const float4*)&A[(long)(row0 + row) * DD + c4 * 4]);
            sA[(c4 * 4 + 0) * 65 + row] = v.x;
            sA[(c4 * 4 + 1) * 65 + row] = v.y;
            sA[(c4 * 4 + 2) * 65 + row] = v.z;
            sA[(c4 * 4 + 3) * 65 + row] = v.w;
        }
        __syncthreads();

#pragma unroll 8
        for (int k = 0; k < DD; ++k) {
            float4 w = ((const float4*)(sW + k * DD))[tx];
            float a0 = sA[k * 65 + ty * 4 + 0];
            float a1 = sA[k * 65 + ty * 4 + 1];
            float a2 = sA[k * 65 + ty * 4 + 2];
            float a3 = sA[k * 65 + ty * 4 + 3];
            acc[0][0] = fmaf(a0, w.x, acc[0][0]);
            acc[0][1] = fmaf(a0, w.y, acc[0][1]);
            acc[0][2] = fmaf(a0, w.z, acc[0][2]);
            acc[0][3] = fmaf(a0, w.w, acc[0][3]);
            acc[1][0] = fmaf(a1, w.x, acc[1][0]);
            acc[1][1] = fmaf(a1, w.y, acc[1][1]);
            acc[1][2] = fmaf(a1, w.z, acc[1][2]);
            acc[1][3] = fmaf(a1, w.w, acc[1][3]);
            acc[2][0] = fmaf(a2, w.x, acc[2][0]);
            acc[2][1] = fmaf(a2, w.y, acc[2][1]);
            acc[2][2] = fmaf(a2, w.z, acc[2][2]);
            acc[2][3] = fmaf(a2, w.w, acc[2][3]);
            acc[3][0] = fmaf(a3, w.x, acc[3][0]);
            acc[3][1] = fmaf(a3, w.y, acc[3][1]);
            acc[3][2] = fmaf(a3, w.z, acc[3][2]);
            acc[3][3] = fmaf(a3, w.w, acc[3][3]);
        }
        __syncthreads();   // protect shared before next pass reload
    }

    // epilogue: bias + tanh + store (float4)
    float4 b = ((const float4*)bl)[tx];
#pragma unroll
    for (int i = 0; i < 4; ++i) {
        int row = row0 + ty * 4 + i;
        if (row < NN) {
            float4 o;
            o.x = tanhf(acc[i][0] + b.x);
            o.y = tanhf(acc[i][1] + b.y);
            o.z = tanhf(acc[i][2] + b.z);
            o.w = tanhf(acc[i][3] + b.w);
            ((float4*)out)[(long)row * (DD / 4) + tx] = o;
        }
    }
}

// ---------------------------------------------------------------------------
// Launch: inputs per metadata order:
//   d_in[0] = x          (100000*64 f32)
//   d_in[1] = edge_index (2*1250000 int32 — JAX x64-disabled)  [row0=src, row1=dst]
//   d_in[2] = W_l (64*64 f32)
//   d_in[3] = b_l (64 f32)
//   d_in[4] = W_r (64*64 f32)
// d_out = 100000*64 f32
// ---------------------------------------------------------------------------
extern "C" void kernel_launch(void* const* d_in, const int* in_sizes, int n_in,
                              void* d_out, int out_size) {
    const float* x   = (const float*)d_in[0];
    const int*   ei  = (const int*)d_in[1];
    const float* Wl  = (const float*)d_in[2];
    const float* bl  = (const float*)d_in[3];
    const float* Wr  = (const float*)d_in[4];
    float*       out = (float*)d_out;

    const int* src = ei;        // edge_index[0]
    const int* dst = ei + NE;   // edge_index[1]

    // 1) zero accumulator: 1.6M float4
    {
        int n4 = NN * (DD / 4);
        zero_aggr_kernel<<<(n4 + 255) / 256, 256>>>();
    }
    // 2) scatter-add: 20M work items (edge x 16B chunk)
    {
        long long items = (long long)NE * 16;
        int blocks = (int)((items + 255) / 256);
        scatter_kernel<<<blocks, 256>>>((const float4*)x, src, dst);
    }
    // 3) fused GEMM + bias + tanh
    {
        int blocks = (NN + 63) / 64;
        fused_gemm_kernel<<<blocks, 256>>>(x, Wl, bl, Wr, out);
    }
}